// round 3
// baseline (speedup 1.0000x reference)
#include <cuda_runtime.h>

// F[8,16384,12] f32 -> out[8,12,16384] f32
#define NV      12
#define SEQ_N   16384
#define ROWS    131072                  // 8 * 16384
#define TOTAL   (ROWS * NV)             // 1572864
#define TPB     128
#define GRID    (ROWS / TPB)            // 1024
#define NEG_SLOPE 0.2f
#define BN_EPS  1e-5

typedef unsigned long long ull;

// Scratch: device globals only (no allocation anywhere). Zero-initialized.
__device__ double2  g_partials[GRID];
__device__ float2   g_coef;
__device__ unsigned g_arrive;           // 0 at each launch start (self-resetting)
__device__ unsigned g_depart;

// ---------------- packed f32x2 helpers (sm_100+ FFMA2 path) ----------------
__device__ __forceinline__ ull pk2(float a, float b) {
    ull r; asm("mov.b64 %0, {%1,%2};" : "=l"(r) : "f"(a), "f"(b)); return r;
}
__device__ __forceinline__ void upk2(ull v, float& a, float& b) {
    asm("mov.b64 {%0,%1}, %2;" : "=f"(a), "=f"(b) : "l"(v));
}
__device__ __forceinline__ ull add2(ull a, ull b) {
    ull r; asm("add.rn.f32x2 %0, %1, %2;" : "=l"(r) : "l"(a), "l"(b)); return r;
}
__device__ __forceinline__ ull mul2(ull a, ull b) {
    ull r; asm("mul.rn.f32x2 %0, %1, %2;" : "=l"(r) : "l"(a), "l"(b)); return r;
}
__device__ __forceinline__ ull fma2(ull a, ull b, ull c) {
    ull r; asm("fma.rn.f32x2 %0, %1, %2, %3;" : "=l"(r) : "l"(a), "l"(b), "l"(c)); return r;
}
// leaky per lane: max(x, 0.2x). Packed mul on fma pipe, 2 scalar FMNMX on alu pipe.
__device__ __forceinline__ ull leaky2(ull v, ull k02) {
    ull t = mul2(v, k02);
    float v0, v1, t0, t1;
    upk2(v, v0, v1); upk2(t, t0, t1);
    return pk2(fmaxf(v0, t0), fmaxf(v1, t1));
}
__device__ __forceinline__ float leaky1(float x) { return fmaxf(x, NEG_SLOPE * x); }

// ---------------------------------------------------------------------------
__global__ __launch_bounds__(TPB, 8)
void nlmp_fused_kernel(const float* __restrict__ F,
                       const float* __restrict__ W1, const float* __restrict__ b1,
                       const float* __restrict__ W2, const float* __restrict__ b2,
                       const float* __restrict__ W3, const float* __restrict__ b3,
                       const float* __restrict__ cw, const float* __restrict__ cb,
                       const float* __restrict__ gamma, const float* __restrict__ beta,
                       float* __restrict__ y)
{
    const int tid = threadIdx.x;
    const int t   = blockIdx.x * TPB + tid;          // row id

    // ---- scalar weights ----
    const float w100 = __ldg(W1 + 0), w101 = __ldg(W1 + 1);
    const float w110 = __ldg(W1 + 2), w111 = __ldg(W1 + 3);
    const float B10  = __ldg(b1 + 0), B11  = __ldg(b1 + 1);
    const float cw0  = __ldg(cw + 0), cw1  = __ldg(cw + 1);
    const float cb0  = __ldg(cb + 0);

    // ---- packed (broadcast) weights for the j-pair lanes ----
    const ull w200d = pk2(__ldg(W2 + 0), __ldg(W2 + 0));
    const ull w201d = pk2(__ldg(W2 + 1), __ldg(W2 + 1));
    const ull w210d = pk2(__ldg(W2 + 2), __ldg(W2 + 2));
    const ull w211d = pk2(__ldg(W2 + 3), __ldg(W2 + 3));
    const ull B20d  = pk2(__ldg(b2 + 0), __ldg(b2 + 0));
    const ull B21d  = pk2(__ldg(b2 + 1), __ldg(b2 + 1));
    const ull w30d  = pk2(__ldg(W3 + 0), __ldg(W3 + 0));
    const ull w31d  = pk2(__ldg(W3 + 1), __ldg(W3 + 1));
    const ull B3d   = pk2(__ldg(b3 + 0), __ldg(b3 + 0));
    const ull k02d  = pk2(NEG_SLOPE, NEG_SLOPE);

    // ---- row features (3x LDG.128) ----
    const float4* fv = reinterpret_cast<const float4*>(F) + (size_t)t * 3;
    const float4 f0 = fv[0], f1 = fv[1], f2 = fv[2];
    const float xs[NV] = { f0.x, f0.y, f0.z, f0.w,
                           f1.x, f1.y, f1.z, f1.w,
                           f2.x, f2.y, f2.z, f2.w };

    // Layer-1 separable precompute, packed over j-pairs:
    //   p_h[j] = W1[h,0]*F[j] + b1[h];  a_h(i,j) = p_h[j] + W1[h,1]*F[i]
    ull P0[NV / 2], P1[NV / 2];
    #pragma unroll
    for (int jj = 0; jj < NV / 2; jj++) {
        P0[jj] = pk2(fmaf(w100, xs[2 * jj], B10), fmaf(w100, xs[2 * jj + 1], B10));
        P1[jj] = pk2(fmaf(w110, xs[2 * jj], B11), fmaf(w110, xs[2 * jj + 1], B11));
    }

    const int b = t >> 14;
    const int n = t & (SEQ_N - 1);
    float* outp = y + ((size_t)b * NV << 14) + n;
    const float* frow = F + (size_t)t * NV;

    float s1 = 0.f, s2 = 0.f;

    #pragma unroll 2
    for (int i = 0; i < NV; i++) {
        const float xi = __ldg(frow + i);            // L1 hit
        const float q0 = w101 * xi;
        const float q1 = w111 * xi;
        const ull q0d = pk2(q0, q0);
        const ull q1d = pk2(q1, q1);
        ull acc = 0ull;                              // packed {0,0}
        #pragma unroll
        for (int jj = 0; jj < NV / 2; jj++) {
            ull a0 = add2(P0[jj], q0d);
            ull a1 = add2(P1[jj], q1d);
            a0 = leaky2(a0, k02d);
            a1 = leaky2(a1, k02d);
            ull g0 = fma2(w200d, a0, fma2(w201d, a1, B20d));
            ull g1 = fma2(w210d, a0, fma2(w211d, a1, B21d));
            g0 = leaky2(g0, k02d);
            g1 = leaky2(g1, k02d);
            ull o = fma2(w30d, g0, fma2(w31d, g1, B3d));
            o = leaky2(o, k02d);
            acc = add2(acc, o);
        }
        float m0, m1; upk2(acc, m0, m1);
        const float Ms = m0 + m1;                    // Msum[b,n,i]
        const float yv = fmaf(cw0, xi, fmaf(cw1, Ms, cb0));
        outp[(size_t)i << 14] = yv;                  // pre-BN value
        s1 += yv;
        s2 = fmaf(yv, yv, s2);
    }

    // ---- deterministic per-block (sum, sumsq) in double ----
    double d1 = (double)s1, d2 = (double)s2;
    #pragma unroll
    for (int o = 16; o > 0; o >>= 1) {
        d1 += __shfl_down_sync(0xffffffffu, d1, o);
        d2 += __shfl_down_sync(0xffffffffu, d2, o);
    }
    __shared__ double sh1[TPB / 32], sh2[TPB / 32];
    const int lane = tid & 31, warp = tid >> 5;
    if (lane == 0) { sh1[warp] = d1; sh2[warp] = d2; }
    __syncthreads();

    __shared__ bool   s_last;
    __shared__ float2 s_coef;
    __shared__ double sred1[TPB], sred2[TPB];

    if (tid == 0) {
        double t1 = 0.0, t2 = 0.0;
        #pragma unroll
        for (int w = 0; w < TPB / 32; w++) { t1 += sh1[w]; t2 += sh2[w]; }
        g_partials[blockIdx.x] = make_double2(t1, t2);
        __threadfence();
        unsigned old = atomicAdd(&g_arrive, 1u);
        s_last = (old == GRID - 1u);
    }
    __syncthreads();

    if (s_last) {
        // Last-arriving block: all partials are globally visible. Reduce them
        // in a fixed order (deterministic) and publish the BN affine coefs.
        __threadfence();                              // acquire partials
        double a = 0.0, c = 0.0;
        const int base = tid * (GRID / TPB);          // 8 partials per thread
        #pragma unroll
        for (int k = 0; k < GRID / TPB; k++) {
            double2 v = g_partials[base + k];
            a += v.x; c += v.y;
        }
        sred1[tid] = a; sred2[tid] = c;
        __syncthreads();
        if (tid == 0) {
            double t1 = 0.0, t2 = 0.0;
            for (int k = 0; k < TPB; k++) { t1 += sred1[k]; t2 += sred2[k]; }
            const double M    = (double)TOTAL;
            const double mean = t1 / M;
            const double var  = t2 / M - mean * mean; // biased
            const double rs   = 1.0 / sqrt(var + BN_EPS);
            const double gm   = (double)__ldg(gamma);
            const float scale = (float)(gm * rs);
            const float shift = (float)((double)__ldg(beta) - mean * gm * rs);
            s_coef = make_float2(scale, shift);
            g_coef = s_coef;
            __threadfence();
            atomicExch(&g_arrive, 2u * GRID);         // release sentinel
        }
        __syncthreads();
    } else {
        if (tid == 0) {
            while (*(volatile unsigned*)&g_arrive != 2u * GRID) __nanosleep(40);
            __threadfence();                          // acquire g_coef
            float cx, cy;
            asm volatile("ld.volatile.global.v2.f32 {%0,%1}, [%2];"
                         : "=f"(cx), "=f"(cy) : "l"(&g_coef));
            s_coef = make_float2(cx, cy);
        }
        __syncthreads();
    }

    // ---- phase 3: normalize + leaky, grid-partitioned float4 sweep (L2 hits) ----
    const float sc = s_coef.x, sf = s_coef.y;
    float4* p = reinterpret_cast<float4*>(y);
    const int g = blockIdx.x * TPB + tid;             // 131072 threads
    #pragma unroll
    for (int k = 0; k < TOTAL / 4 / ROWS; k++) {      // 3 float4 each
        const int idx = g + k * ROWS;
        float4 v = p[idx];
        v.x = leaky1(fmaf(v.x, sc, sf));
        v.y = leaky1(fmaf(v.y, sc, sf));
        v.z = leaky1(fmaf(v.z, sc, sf));
        v.w = leaky1(fmaf(v.w, sc, sf));
        p[idx] = v;
    }

    // ---- self-reset for the next graph replay ----
    if (tid == 0) {
        unsigned old = atomicAdd(&g_depart, 1u);
        if (old == GRID - 1u) {
            g_arrive = 0u;
            g_depart = 0u;
            __threadfence();
        }
    }
}

// ---------------------------------------------------------------------------
extern "C" void kernel_launch(void* const* d_in, const int* in_sizes, int n_in,
                              void* d_out, int out_size)
{
    const float* F    = (const float*)d_in[0];
    const float* W1   = (const float*)d_in[1];
    const float* b1   = (const float*)d_in[2];
    const float* W2   = (const float*)d_in[3];
    const float* b2   = (const float*)d_in[4];
    const float* W3   = (const float*)d_in[5];
    const float* b3   = (const float*)d_in[6];
    const float* cw   = (const float*)d_in[7];
    const float* cb   = (const float*)d_in[8];
    const float* gmma = (const float*)d_in[9];
    const float* beta = (const float*)d_in[10];
    float* out = (float*)d_out;

    nlmp_fused_kernel<<<GRID, TPB>>>(F, W1, b1, W2, b2, W3, b3, cw, cb,
                                     gmma, beta, out);
}

// round 4
// speedup vs baseline: 1.3007x; 1.3007x over previous
#include <cuda_runtime.h>

// F[8,16384,12] f32 -> out [8,12,16384] f32
#define NV      12
#define SEQ_N   16384
#define ROWS    131072                  // 8 * 16384
#define TOTAL   (ROWS * NV)             // 1572864
#define TPB_A   128
#define NBLK_A  (ROWS / TPB_A)          // 1024
#define NEG_SLOPE 0.2f
#define BN_EPS  1e-5

typedef unsigned long long ull;

// Scratch: device globals only.
__device__ double2 g_partials[NBLK_A];
__device__ float2  g_coef;

// ---------------- packed f32x2 helpers (sm_103a FFMA2 path) ----------------
__device__ __forceinline__ ull pk2(float a, float b) {
    ull r; asm("mov.b64 %0, {%1,%2};" : "=l"(r) : "f"(a), "f"(b)); return r;
}
__device__ __forceinline__ void upk2(ull v, float& a, float& b) {
    asm("mov.b64 {%0,%1}, %2;" : "=f"(a), "=f"(b) : "l"(v));
}
__device__ __forceinline__ ull add2(ull a, ull b) {
    ull r; asm("add.rn.f32x2 %0, %1, %2;" : "=l"(r) : "l"(a), "l"(b)); return r;
}
__device__ __forceinline__ ull mul2(ull a, ull b) {
    ull r; asm("mul.rn.f32x2 %0, %1, %2;" : "=l"(r) : "l"(a), "l"(b)); return r;
}
__device__ __forceinline__ ull fma2(ull a, ull b, ull c) {
    ull r; asm("fma.rn.f32x2 %0, %1, %2, %3;" : "=l"(r) : "l"(a), "l"(b), "l"(c)); return r;
}
// leaky per lane: max(x, 0.2x) = 1 packed FMUL2 + 2 scalar FMNMX (alu pipe).
__device__ __forceinline__ ull leaky2(ull v, ull k02) {
    ull t = mul2(v, k02);
    float v0, v1, t0, t1;
    upk2(v, v0, v1); upk2(t, t0, t1);
    return pk2(fmaxf(v0, t0), fmaxf(v1, t1));
}
__device__ __forceinline__ float leaky1(float x) { return fmaxf(x, NEG_SLOPE * x); }

// ---------------------------------------------------------------------------
// Kernel A: pair-MLP + conv, write pre-BN y, deterministic per-block sums.
// ---------------------------------------------------------------------------
__global__ __launch_bounds__(TPB_A)
void nlmp_main_kernel(const float* __restrict__ F,
                      const float* __restrict__ W1, const float* __restrict__ b1,
                      const float* __restrict__ W2, const float* __restrict__ b2,
                      const float* __restrict__ W3, const float* __restrict__ b3,
                      const float* __restrict__ cw, const float* __restrict__ cb,
                      float* __restrict__ y)
{
    const int tid = threadIdx.x;
    const int t   = blockIdx.x * TPB_A + tid;        // row id

    // ---- scalar weights ----
    const float w100 = __ldg(W1 + 0), w101 = __ldg(W1 + 1);
    const float w110 = __ldg(W1 + 2), w111 = __ldg(W1 + 3);
    const float B10  = __ldg(b1 + 0), B11  = __ldg(b1 + 1);
    const float cw0  = __ldg(cw + 0), cw1  = __ldg(cw + 1);
    const float cb0  = __ldg(cb + 0);

    // ---- packed (broadcast) weights ----
    const ull w200d = pk2(__ldg(W2 + 0), __ldg(W2 + 0));
    const ull w201d = pk2(__ldg(W2 + 1), __ldg(W2 + 1));
    const ull w210d = pk2(__ldg(W2 + 2), __ldg(W2 + 2));
    const ull w211d = pk2(__ldg(W2 + 3), __ldg(W2 + 3));
    const ull B20d  = pk2(__ldg(b2 + 0), __ldg(b2 + 0));
    const ull B21d  = pk2(__ldg(b2 + 1), __ldg(b2 + 1));
    const ull w30d  = pk2(__ldg(W3 + 0), __ldg(W3 + 0));
    const ull w31d  = pk2(__ldg(W3 + 1), __ldg(W3 + 1));
    const ull B3d   = pk2(__ldg(b3 + 0), __ldg(b3 + 0));
    const ull k02d  = pk2(NEG_SLOPE, NEG_SLOPE);

    // ---- row features (3x LDG.128) ----
    const float4* fv = reinterpret_cast<const float4*>(F) + (size_t)t * 3;
    const float4 f0 = fv[0], f1 = fv[1], f2 = fv[2];
    const float xs[NV] = { f0.x, f0.y, f0.z, f0.w,
                           f1.x, f1.y, f1.z, f1.w,
                           f2.x, f2.y, f2.z, f2.w };

    // Layer-1 separable precompute, packed over j-pairs:
    //   p_h[j] = W1[h,0]*F[j] + b1[h];  a_h(i,j) = p_h[j] + W1[h,1]*F[i]
    ull P0[NV / 2], P1[NV / 2];
    #pragma unroll
    for (int jj = 0; jj < NV / 2; jj++) {
        P0[jj] = pk2(fmaf(w100, xs[2 * jj], B10), fmaf(w100, xs[2 * jj + 1], B10));
        P1[jj] = pk2(fmaf(w110, xs[2 * jj], B11), fmaf(w110, xs[2 * jj + 1], B11));
    }

    const int b = t >> 14;
    const int n = t & (SEQ_N - 1);
    float* outp = y + ((size_t)b * NV << 14) + n;
    const float* frow = F + (size_t)t * NV;

    float s1 = 0.f, s2 = 0.f;

    #pragma unroll 2
    for (int i = 0; i < NV; i++) {
        const float xi = __ldg(frow + i);            // L1 hit
        const float q0 = w101 * xi;
        const float q1 = w111 * xi;
        const ull q0d = pk2(q0, q0);
        const ull q1d = pk2(q1, q1);
        ull acc = 0ull;                              // packed {0,0}
        #pragma unroll
        for (int jj = 0; jj < NV / 2; jj++) {
            ull a0 = add2(P0[jj], q0d);
            ull a1 = add2(P1[jj], q1d);
            a0 = leaky2(a0, k02d);
            a1 = leaky2(a1, k02d);
            ull g0 = fma2(w200d, a0, fma2(w201d, a1, B20d));
            ull g1 = fma2(w210d, a0, fma2(w211d, a1, B21d));
            g0 = leaky2(g0, k02d);
            g1 = leaky2(g1, k02d);
            ull o = fma2(w30d, g0, fma2(w31d, g1, B3d));
            o = leaky2(o, k02d);
            acc = add2(acc, o);
        }
        float m0, m1; upk2(acc, m0, m1);
        const float Ms = m0 + m1;                    // Msum[b,n,i]
        const float yv = fmaf(cw0, xi, fmaf(cw1, Ms, cb0));
        outp[(size_t)i << 14] = yv;                  // coalesced
        s1 += yv;
        s2 = fmaf(yv, yv, s2);
    }

    // ---- deterministic per-block (sum, sumsq) in double ----
    double d1 = (double)s1, d2 = (double)s2;
    #pragma unroll
    for (int o = 16; o > 0; o >>= 1) {
        d1 += __shfl_down_sync(0xffffffffu, d1, o);
        d2 += __shfl_down_sync(0xffffffffu, d2, o);
    }
    __shared__ double sh1[TPB_A / 32], sh2[TPB_A / 32];
    const int lane = tid & 31, warp = tid >> 5;
    if (lane == 0) { sh1[warp] = d1; sh2[warp] = d2; }
    __syncthreads();
    if (tid == 0) {
        double t1 = 0.0, t2 = 0.0;
        #pragma unroll
        for (int w = 0; w < TPB_A / 32; w++) { t1 += sh1[w]; t2 += sh2[w]; }
        g_partials[blockIdx.x] = make_double2(t1, t2);
    }
}

// ---------------------------------------------------------------------------
// Kernel B: reduce 1024 partials -> BN affine (scale, shift). 1 block.
// ---------------------------------------------------------------------------
__global__ __launch_bounds__(1024)
void nlmp_stats_kernel(const float* __restrict__ gamma, const float* __restrict__ beta)
{
    const int tid = threadIdx.x;           // 1024 threads, one partial each
    double2 v = g_partials[tid];
    double d1 = v.x, d2 = v.y;
    #pragma unroll
    for (int o = 16; o > 0; o >>= 1) {
        d1 += __shfl_down_sync(0xffffffffu, d1, o);
        d2 += __shfl_down_sync(0xffffffffu, d2, o);
    }
    __shared__ double sh1[32], sh2[32];
    const int lane = tid & 31, warp = tid >> 5;
    if (lane == 0) { sh1[warp] = d1; sh2[warp] = d2; }
    __syncthreads();
    if (tid < 32) {
        d1 = sh1[tid];
        d2 = sh2[tid];
        #pragma unroll
        for (int o = 16; o > 0; o >>= 1) {
            d1 += __shfl_down_sync(0xffffffffu, d1, o);
            d2 += __shfl_down_sync(0xffffffffu, d2, o);
        }
        if (tid == 0) {
            const double M    = (double)TOTAL;
            const double mean = d1 / M;
            const double var  = d2 / M - mean * mean;   // biased
            const double rs   = 1.0 / sqrt(var + BN_EPS);
            const double gm   = (double)__ldg(gamma);
            const float scale = (float)(gm * rs);
            const float shift = (float)((double)__ldg(beta) - mean * gm * rs);
            g_coef = make_float2(scale, shift);
        }
    }
}

// ---------------------------------------------------------------------------
// Kernel C: in-place normalize + leaky over d_out (L2-resident).
// ---------------------------------------------------------------------------
__global__ __launch_bounds__(256)
void nlmp_norm_kernel(float* __restrict__ y)
{
    const float2 c = g_coef;               // uniform load
    const int idx = blockIdx.x * 256 + threadIdx.x;   // TOTAL/4 float4s
    float4* p = reinterpret_cast<float4*>(y);
    float4 v = p[idx];
    v.x = leaky1(fmaf(v.x, c.x, c.y));
    v.y = leaky1(fmaf(v.y, c.x, c.y));
    v.z = leaky1(fmaf(v.z, c.x, c.y));
    v.w = leaky1(fmaf(v.w, c.x, c.y));
    p[idx] = v;
}

// ---------------------------------------------------------------------------
extern "C" void kernel_launch(void* const* d_in, const int* in_sizes, int n_in,
                              void* d_out, int out_size)
{
    const float* F    = (const float*)d_in[0];
    const float* W1   = (const float*)d_in[1];
    const float* b1   = (const float*)d_in[2];
    const float* W2   = (const float*)d_in[3];
    const float* b2   = (const float*)d_in[4];
    const float* W3   = (const float*)d_in[5];
    const float* b3   = (const float*)d_in[6];
    const float* cw   = (const float*)d_in[7];
    const float* cb   = (const float*)d_in[8];
    const float* gmma = (const float*)d_in[9];
    const float* beta = (const float*)d_in[10];
    float* out = (float*)d_out;

    nlmp_main_kernel<<<NBLK_A, TPB_A>>>(F, W1, b1, W2, b2, W3, b3, cw, cb, out);
    nlmp_stats_kernel<<<1, 1024>>>(gmma, beta);
    nlmp_norm_kernel<<<(TOTAL / 4) / 256, 256>>>(out);
}